// round 8
// baseline (speedup 1.0000x reference)
#include <cuda_runtime.h>
#include <cuda_bf16.h>

// WCSS: loss = mean_k [ (S2_k - ||S1_k||^2 / n_k) / (n_k * D) ]
//
// R7 post-mortem: main sustained only ~4 lines in flight/warp (LDG.32,
// address chain + reg reuse). R8: float4 columns (LDG.128 = 4x bytes per
// outstanding load), PF=12 double buffer -> ~6KB/warp in flight -> DRAM
// bound. Scatter: batch label loads into registers (both phases reuse).

#define TPB   64           // threads per main block (2 warps)
#define CPB   (TPB * 4)    // columns per block (float4 per thread)
#define SROWS 2048         // row ids staged per segment (8KB smem)
#define PF    12           // pipelined float4 loads per stage
#define KMAX  16           // max classes (problem uses 10)
#define NMAX  16384        // max N (problem uses 8192)
#define SW    32           // warps in scatter block

__device__ double g_S2[KMAX];     // per-class sum of squares
__device__ double g_M2[KMAX];     // per-class ||S1_k||^2
__device__ int    g_order[NMAX];  // row ids grouped by class
__device__ int    g_cnt[KMAX];
__device__ int    g_start[KMAX];

// ---------------------------------------------------------------------------
// One block (1024 thr): batched label loads -> per-warp histograms ->
// prefix -> scatter (labels reused from registers, no reload).
__global__ void wcss_scatter(const int* __restrict__ y, int N)
{
    __shared__ int wcnt[SW][KMAX];
    __shared__ int cls_tot[KMAX];
    __shared__ int start_sh[KMAX];

    const int tid  = threadIdx.x;
    const int w    = tid >> 5;
    const int lane = tid & 31;

    if (lane < KMAX) wcnt[w][lane] = 0;
    if (tid < KMAX) { g_S2[tid] = 0.0; g_M2[tid] = 0.0; }
    __syncthreads();

    // Batched label loads (independent LDGs, one latency).
    int yv[NMAX / 1024];
    #pragma unroll
    for (int j = 0; j < NMAX / 1024; j++) {
        int i = tid + j * 1024;
        yv[j] = (i < N) ? (y[i] & (KMAX - 1)) : -1;
    }

    // Phase 1: per-warp histogram.
    #pragma unroll
    for (int j = 0; j < NMAX / 1024; j++)
        if (yv[j] >= 0) atomicAdd(&wcnt[w][yv[j]], 1);
    __syncthreads();

    // Phase 2: within-class exclusive prefix over warps.
    if (tid < KMAX) {
        int acc = 0;
        for (int w2 = 0; w2 < SW; w2++) {
            int v = wcnt[w2][tid];
            wcnt[w2][tid] = acc;
            acc += v;
        }
        cls_tot[tid] = acc;
    }
    __syncthreads();
    if (tid == 0) {
        int acc = 0;
        for (int k = 0; k < KMAX; k++) {
            start_sh[k] = acc; g_start[k] = acc; g_cnt[k] = cls_tot[k];
            acc += cls_tot[k];
        }
    }
    __syncthreads();
    if (lane < KMAX) wcnt[w][lane] += start_sh[lane];
    __syncthreads();

    // Phase 3: scatter (labels already in registers).
    #pragma unroll
    for (int j = 0; j < NMAX / 1024; j++) {
        if (yv[j] >= 0) {
            int pos = atomicAdd(&wcnt[w][yv[j]], 1);
            if (pos < NMAX) g_order[pos] = tid + j * 1024;
        }
    }
}

// ---------------------------------------------------------------------------
// grid = (colChunks, KMAX). Block (x, c): class c, 4 columns per thread
// (float4). Double-buffered PF-deep LDG.128 pipeline -> DRAM-bound.
__global__ __launch_bounds__(TPB)
void wcss_main(const float* __restrict__ X, int D)
{
    const int c  = blockIdx.y;
    const int cn = g_cnt[c];
    if (cn == 0) return;
    const int st = g_start[c];

    const int tid = threadIdx.x;
    const int d4  = blockIdx.x * CPB + tid * 4;
    const bool v4  = (d4 + 3 < D) && ((D & 3) == 0);
    const bool anyv = (d4 < D);

    __shared__ int rows_sh[SROWS];

    float4 s = make_float4(0.f, 0.f, 0.f, 0.f);
    float4 q = make_float4(0.f, 0.f, 0.f, 0.f);

    for (int seg = 0; seg < cn; seg += SROWS) {
        const int len = min(SROWS, cn - seg);
        __syncthreads();
        for (int i = tid; i < len; i += TPB)
            rows_sh[i] = g_order[st + seg + i];
        __syncthreads();

        if (v4) {
            const char* __restrict__ basep =
                (const char*)(X + d4);

            float4 buf[PF];
            const int np = min(PF, len);
            #pragma unroll
            for (int u = 0; u < PF; u++)
                buf[u] = (u < np)
                    ? __ldg((const float4*)(basep + (size_t)rows_sh[u] * D * 4))
                    : make_float4(0.f, 0.f, 0.f, 0.f);

            int i = 0;
            for (; i + 2 * PF <= len; i += PF) {
                float4 nxt[PF];
                #pragma unroll
                for (int u = 0; u < PF; u++)     // issue next batch FIRST
                    nxt[u] = __ldg((const float4*)(basep +
                                   (size_t)rows_sh[i + PF + u] * D * 4));
                #pragma unroll
                for (int u = 0; u < PF; u++) {   // consume current batch
                    float4 x = buf[u];
                    s.x += x.x; q.x = fmaf(x.x, x.x, q.x);
                    s.y += x.y; q.y = fmaf(x.y, x.y, q.y);
                    s.z += x.z; q.z = fmaf(x.z, x.z, q.z);
                    s.w += x.w; q.w = fmaf(x.w, x.w, q.w);
                }
                #pragma unroll
                for (int u = 0; u < PF; u++)
                    buf[u] = nxt[u];
            }

            const int inbuf = min(PF, len - i);
            #pragma unroll
            for (int u = 0; u < PF; u++) {
                if (u < inbuf) {
                    float4 x = buf[u];
                    s.x += x.x; q.x = fmaf(x.x, x.x, q.x);
                    s.y += x.y; q.y = fmaf(x.y, x.y, q.y);
                    s.z += x.z; q.z = fmaf(x.z, x.z, q.z);
                    s.w += x.w; q.w = fmaf(x.w, x.w, q.w);
                }
            }
            for (int j = i + inbuf; j < len; j++) {
                float4 x = __ldg((const float4*)(basep +
                                 (size_t)rows_sh[j] * D * 4));
                s.x += x.x; q.x = fmaf(x.x, x.x, q.x);
                s.y += x.y; q.y = fmaf(x.y, x.y, q.y);
                s.z += x.z; q.z = fmaf(x.z, x.z, q.z);
                s.w += x.w; q.w = fmaf(x.w, x.w, q.w);
            }
        } else if (anyv) {
            // Tail columns (or D not multiple of 4): scalar per column.
            const int ncols = min(4, D - d4);
            for (int i = 0; i < len; i++) {
                const float* rp = X + (size_t)rows_sh[i] * D + d4;
                #pragma unroll 4
                for (int cc = 0; cc < ncols; cc++) {
                    float xv = __ldg(rp + cc);
                    ((float*)&s)[cc] += xv;
                    ((float*)&q)[cc] = fmaf(xv, xv, ((float*)&q)[cc]);
                }
            }
        }
    }

    // Per-thread: m2 = sum of squared column sums; qt = sumsq.
    float m2 = s.x * s.x + s.y * s.y + s.z * s.z + s.w * s.w;
    float qt = (q.x + q.y) + (q.z + q.w);

    #pragma unroll
    for (int o = 16; o > 0; o >>= 1) {
        m2 += __shfl_down_sync(0xffffffffu, m2, o);
        qt += __shfl_down_sync(0xffffffffu, qt, o);
    }

    __shared__ float ms[TPB / 32], qs[TPB / 32];
    if ((tid & 31) == 0) { ms[tid >> 5] = m2; qs[tid >> 5] = qt; }
    __syncthreads();
    if (tid == 0) {
        float mv = 0.f, qv = 0.f;
        #pragma unroll
        for (int w = 0; w < TPB / 32; w++) { mv += ms[w]; qv += qs[w]; }
        atomicAdd(&g_M2[c], (double)mv);
        atomicAdd(&g_S2[c], (double)qv);
    }
}

// ---------------------------------------------------------------------------
__global__ void wcss_final(int D, float* __restrict__ out)
{
    if (threadIdx.x == 0) {
        double total = 0.0;
        int    nc    = 0;
        for (int k = 0; k < KMAX; k++) {
            int c = g_cnt[k];
            if (c == 0) continue;
            double n = (double)c;
            total += (g_S2[k] - g_M2[k] / n) / (n * (double)D);
            nc++;
        }
        out[0] = (float)(total / (double)(nc > 0 ? nc : 1));
    }
}

// ---------------------------------------------------------------------------
extern "C" void kernel_launch(void* const* d_in, const int* in_sizes, int n_in,
                              void* d_out, int out_size)
{
    const float* X   = (const float*)d_in[0];
    const int*   y   = (const int*)d_in[1];   // int32 (JAX x64 disabled)
    float*       out = (float*)d_out;

    const int total = in_sizes[0];          // N * C * T
    const int N     = in_sizes[1];          // 8192
    const int D     = total / N;            // 6144

    wcss_scatter<<<1, 1024>>>(y, N);

    {
        int chunks = (D + CPB - 1) / CPB;   // 24
        dim3 grid(chunks, KMAX);
        wcss_main<<<grid, TPB>>>(X, D);
    }

    wcss_final<<<1, 32>>>(D, out);
}

// round 9
// speedup vs baseline: 1.1437x; 1.1437x over previous
#include <cuda_runtime.h>
#include <cuda_bf16.h>

// WCSS: loss = mean_k [ (S2_k - ||S1_k||^2 / n_k) / (n_k * D) ]
//
// R8 post-mortem: float4@TPB=64 crashed warps/SM (3.2) -> 2.8TB/s. The
// controlling variable is (warps/SM) x (lines in flight per warp).
// R9: float2 @ TPB=128 (6.5 warps/SM x 32 lines = queue-cap), PF=16 double
// buffer, and the class row-list is compacted by each block directly from y
// (L2-resident) -> scatter kernel and g_order eliminated entirely.

#define TPB   128          // threads per main block (4 warps)
#define CPB   (TPB * 2)    // columns per block (float2 per thread)
#define RCAP  1536         // row-id capacity in smem (class ~820 rows)
#define PF    16           // pipelined float2 loads per stage
#define KMAX  16           // max classes (problem uses 10)

__device__ double g_S2[KMAX];     // per-class sum of squares
__device__ double g_M2[KMAX];     // per-class ||S1_k||^2
__device__ int    g_cnt[KMAX];

// ---------------------------------------------------------------------------
// Zero the tiny per-class accumulators (graph-replay safe).
__global__ void wcss_zero()
{
    if (threadIdx.x < KMAX) {
        g_S2[threadIdx.x] = 0.0;
        g_M2[threadIdx.x] = 0.0;
        g_cnt[threadIdx.x] = 0;
    }
}

// ---------------------------------------------------------------------------
// grid = (colChunks, KMAX). Block (x, c): class c, 2 columns per thread.
// Step 1: compact this class's row ids from y into smem (batched loads).
// Step 2: double-buffered PF-deep LDG.64 pipeline, register-complete
//         column sums -> 2 double atomics per block.
__global__ __launch_bounds__(TPB)
void wcss_main(const float* __restrict__ X, const int* __restrict__ y,
               int N, int D)
{
    const int c   = blockIdx.y;
    const int tid = threadIdx.x;

    __shared__ int rows_sh[RCAP];
    __shared__ int nrows_sh;
    if (tid == 0) nrows_sh = 0;
    __syncthreads();

    // --- Compaction: 8-way batched label loads, smem append ---
    for (int base = tid; base < N; base += TPB * 8) {
        int lab[8];
        #pragma unroll
        for (int u = 0; u < 8; u++) {
            int i = base + u * TPB;
            lab[u] = (i < N) ? (__ldg(&y[i]) & (KMAX - 1)) : -1;
        }
        #pragma unroll
        for (int u = 0; u < 8; u++) {
            if (lab[u] == c) {
                int p = atomicAdd(&nrows_sh, 1);
                if (p < RCAP) rows_sh[p] = base + u * TPB;
            }
        }
    }
    __syncthreads();
    const int cn = min(nrows_sh, RCAP);
    if (blockIdx.x == 0 && tid == 0) g_cnt[c] = cn;
    if (cn == 0) return;

    const int d2 = blockIdx.x * CPB + tid * 2;
    const bool v2 = (d2 + 1 < D) && ((D & 1) == 0);

    float2 s = make_float2(0.f, 0.f);
    float2 q = make_float2(0.f, 0.f);

    if (v2) {
        const char* __restrict__ basep = (const char*)(X + d2);
        const size_t stride = (size_t)D * 4;

        float2 buf[PF];
        const int np = min(PF, cn);
        #pragma unroll
        for (int u = 0; u < PF; u++)
            buf[u] = (u < np)
                ? __ldg((const float2*)(basep + (size_t)rows_sh[u] * stride))
                : make_float2(0.f, 0.f);

        int i = 0;
        for (; i + 2 * PF <= cn; i += PF) {
            float2 nxt[PF];
            #pragma unroll
            for (int u = 0; u < PF; u++)          // issue next batch FIRST
                nxt[u] = __ldg((const float2*)(basep +
                               (size_t)rows_sh[i + PF + u] * stride));
            #pragma unroll
            for (int u = 0; u < PF; u++) {        // consume current batch
                float2 x = buf[u];
                s.x += x.x; q.x = fmaf(x.x, x.x, q.x);
                s.y += x.y; q.y = fmaf(x.y, x.y, q.y);
            }
            #pragma unroll
            for (int u = 0; u < PF; u++)
                buf[u] = nxt[u];
        }

        const int inbuf = min(PF, cn - i);
        #pragma unroll
        for (int u = 0; u < PF; u++) {
            if (u < inbuf) {
                float2 x = buf[u];
                s.x += x.x; q.x = fmaf(x.x, x.x, q.x);
                s.y += x.y; q.y = fmaf(x.y, x.y, q.y);
            }
        }
        for (int j = i + inbuf; j < cn; j++) {
            float2 x = __ldg((const float2*)(basep +
                             (size_t)rows_sh[j] * stride));
            s.x += x.x; q.x = fmaf(x.x, x.x, q.x);
            s.y += x.y; q.y = fmaf(x.y, x.y, q.y);
        }
    } else if (d2 < D) {
        // Tail / odd-D fallback: scalar per column.
        const int ncols = min(2, D - d2);
        for (int i = 0; i < cn; i++) {
            const float* rp = X + (size_t)rows_sh[i] * D + d2;
            for (int cc = 0; cc < ncols; cc++) {
                float xv = __ldg(rp + cc);
                ((float*)&s)[cc] += xv;
                ((float*)&q)[cc] = fmaf(xv, xv, ((float*)&q)[cc]);
            }
        }
    }

    // Per-thread: m2 = squared column sums; qt = sumsq.
    float m2 = s.x * s.x + s.y * s.y;
    float qt = q.x + q.y;

    #pragma unroll
    for (int o = 16; o > 0; o >>= 1) {
        m2 += __shfl_down_sync(0xffffffffu, m2, o);
        qt += __shfl_down_sync(0xffffffffu, qt, o);
    }

    __shared__ float ms[TPB / 32], qs[TPB / 32];
    if ((tid & 31) == 0) { ms[tid >> 5] = m2; qs[tid >> 5] = qt; }
    __syncthreads();
    if (tid == 0) {
        float mv = 0.f, qv = 0.f;
        #pragma unroll
        for (int w = 0; w < TPB / 32; w++) { mv += ms[w]; qv += qs[w]; }
        atomicAdd(&g_M2[c], (double)mv);
        atomicAdd(&g_S2[c], (double)qv);
    }
}

// ---------------------------------------------------------------------------
__global__ void wcss_final(int D, float* __restrict__ out)
{
    if (threadIdx.x == 0) {
        double total = 0.0;
        int    nc    = 0;
        for (int k = 0; k < KMAX; k++) {
            int c = g_cnt[k];
            if (c == 0) continue;
            double n = (double)c;
            total += (g_S2[k] - g_M2[k] / n) / (n * (double)D);
            nc++;
        }
        out[0] = (float)(total / (double)(nc > 0 ? nc : 1));
    }
}

// ---------------------------------------------------------------------------
extern "C" void kernel_launch(void* const* d_in, const int* in_sizes, int n_in,
                              void* d_out, int out_size)
{
    const float* X   = (const float*)d_in[0];
    const int*   y   = (const int*)d_in[1];   // int32 (JAX x64 disabled)
    float*       out = (float*)d_out;

    const int total = in_sizes[0];          // N * C * T
    const int N     = in_sizes[1];          // 8192
    const int D     = total / N;            // 6144

    wcss_zero<<<1, 32>>>();

    {
        int chunks = (D + CPB - 1) / CPB;   // 24
        dim3 grid(chunks, KMAX);
        wcss_main<<<grid, TPB>>>(X, y, N, D);
    }

    wcss_final<<<1, 32>>>(D, out);
}

// round 10
// speedup vs baseline: 1.3802x; 1.2068x over previous
#include <cuda_runtime.h>
#include <cuda_bf16.h>

// WCSS: loss = mean_k [ (S2_k - ||S1_k||^2 / n_k) / (n_k * D) ]
//
// R9 post-mortem (clock-corrected model): the nxt->buf register copy
// serialized batches -> only ONE 16-deep batch in flight per warp
// (~3.9GB/s/warp @NAT) -> main ~60us. R10: true ping-pong with two
// independent buffers, no copy -> TWO batches (8KB) in flight per warp
// continuously -> demand ~9TB/s -> DRAM-capped. rows_sh holds byte
// offsets (one less IMAD on the address chain).

#define TPB   128          // threads per main block (4 warps)
#define CPB   (TPB * 2)    // columns per block (float2 per thread)
#define RCAP  1536         // row capacity in smem (class ~820 rows)
#define PF    16           // loads per pipeline stage
#define KMAX  16           // max classes (problem uses 10)

__device__ double g_S2[KMAX];     // per-class sum of squares
__device__ double g_M2[KMAX];     // per-class ||S1_k||^2
__device__ int    g_cnt[KMAX];

// ---------------------------------------------------------------------------
__global__ void wcss_zero()
{
    if (threadIdx.x < KMAX) {
        g_S2[threadIdx.x] = 0.0;
        g_M2[threadIdx.x] = 0.0;
        g_cnt[threadIdx.x] = 0;
    }
}

// ---------------------------------------------------------------------------
// grid = (colChunks, KMAX). Block (x, c): class c, 2 columns per thread.
// Step 1: compact this class's row byte-offsets from y into smem.
// Step 2: two-stage ping-pong LDG.64 pipeline (2 batches in flight),
//         register-complete column sums -> 2 double atomics per block.
__global__ __launch_bounds__(TPB)
void wcss_main(const float* __restrict__ X, const int* __restrict__ y,
               int N, int D)
{
    const int c   = blockIdx.y;
    const int tid = threadIdx.x;

    __shared__ size_t rows_sh[RCAP];   // byte offsets: row * D * 4
    __shared__ int nrows_sh;
    if (tid == 0) nrows_sh = 0;
    __syncthreads();

    const size_t stride = (size_t)D * 4;

    // --- Compaction: 8-way batched label loads, smem append ---
    for (int base = tid; base < N; base += TPB * 8) {
        int lab[8];
        #pragma unroll
        for (int u = 0; u < 8; u++) {
            int i = base + u * TPB;
            lab[u] = (i < N) ? (__ldg(&y[i]) & (KMAX - 1)) : -1;
        }
        #pragma unroll
        for (int u = 0; u < 8; u++) {
            if (lab[u] == c) {
                int p = atomicAdd(&nrows_sh, 1);
                if (p < RCAP) rows_sh[p] = (size_t)(base + u * TPB) * stride;
            }
        }
    }
    __syncthreads();
    const int cn = min(nrows_sh, RCAP);
    if (blockIdx.x == 0 && tid == 0) g_cnt[c] = cn;
    if (cn == 0) return;

    const int d2 = blockIdx.x * CPB + tid * 2;
    const bool v2 = (d2 + 1 < D) && ((D & 1) == 0);

    float2 s = make_float2(0.f, 0.f);
    float2 q = make_float2(0.f, 0.f);

    if (v2) {
        const char* __restrict__ basep = (const char*)(X + d2);

        float2 b0[PF], b1[PF];
        const int nb = cn / PF;             // full batches

        #define LOADB(B, BATCH) do {                                         \
            const int _o = (BATCH) * PF;                                     \
            _Pragma("unroll")                                                \
            for (int _u = 0; _u < PF; _u++)                                  \
                (B)[_u] = __ldg((const float2*)(basep + rows_sh[_o + _u]));  \
        } while (0)

        #define CONSB(B) do {                                                \
            _Pragma("unroll")                                                \
            for (int _u = 0; _u < PF; _u++) {                                \
                float2 _x = (B)[_u];                                         \
                s.x += _x.x; q.x = fmaf(_x.x, _x.x, q.x);                    \
                s.y += _x.y; q.y = fmaf(_x.y, _x.y, q.y);                    \
            }                                                                \
        } while (0)

        if (nb > 0) LOADB(b0, 0);
        if (nb > 1) LOADB(b1, 1);

        int bi = 0;
        for (; bi + 4 <= nb; bi += 2) {
            CONSB(b0); LOADB(b0, bi + 2);   // batch bi+3 still issuable next
            CONSB(b1); LOADB(b1, bi + 3);
        }
        // Drain: nb - bi in {0,1,2,3}; b0 holds batch bi, b1 holds bi+1.
        if (nb - bi == 3) {
            CONSB(b0); LOADB(b0, bi + 2);
            CONSB(b1);
            CONSB(b0);
        } else if (nb - bi == 2) {
            CONSB(b0); CONSB(b1);
        } else if (nb - bi == 1) {
            CONSB(b0);
        }

        // Tail rows (< PF).
        for (int j = nb * PF; j < cn; j++) {
            float2 x = __ldg((const float2*)(basep + rows_sh[j]));
            s.x += x.x; q.x = fmaf(x.x, x.x, q.x);
            s.y += x.y; q.y = fmaf(x.y, x.y, q.y);
        }
        #undef LOADB
        #undef CONSB
    } else if (d2 < D) {
        // Tail / odd-D fallback: scalar per column.
        const int ncols = min(2, D - d2);
        for (int i = 0; i < cn; i++) {
            const float* rp = (const float*)((const char*)X + rows_sh[i]) + d2;
            for (int cc = 0; cc < ncols; cc++) {
                float xv = __ldg(rp + cc);
                ((float*)&s)[cc] += xv;
                ((float*)&q)[cc] = fmaf(xv, xv, ((float*)&q)[cc]);
            }
        }
    }

    // Per-thread: m2 = squared column sums; qt = sumsq.
    float m2 = s.x * s.x + s.y * s.y;
    float qt = q.x + q.y;

    #pragma unroll
    for (int o = 16; o > 0; o >>= 1) {
        m2 += __shfl_down_sync(0xffffffffu, m2, o);
        qt += __shfl_down_sync(0xffffffffu, qt, o);
    }

    __shared__ float ms[TPB / 32], qs[TPB / 32];
    if ((tid & 31) == 0) { ms[tid >> 5] = m2; qs[tid >> 5] = qt; }
    __syncthreads();
    if (tid == 0) {
        float mv = 0.f, qv = 0.f;
        #pragma unroll
        for (int w = 0; w < TPB / 32; w++) { mv += ms[w]; qv += qs[w]; }
        atomicAdd(&g_M2[c], (double)mv);
        atomicAdd(&g_S2[c], (double)qv);
    }
}

// ---------------------------------------------------------------------------
__global__ void wcss_final(int D, float* __restrict__ out)
{
    if (threadIdx.x == 0) {
        double total = 0.0;
        int    nc    = 0;
        for (int k = 0; k < KMAX; k++) {
            int c = g_cnt[k];
            if (c == 0) continue;
            double n = (double)c;
            total += (g_S2[k] - g_M2[k] / n) / (n * (double)D);
            nc++;
        }
        out[0] = (float)(total / (double)(nc > 0 ? nc : 1));
    }
}

// ---------------------------------------------------------------------------
extern "C" void kernel_launch(void* const* d_in, const int* in_sizes, int n_in,
                              void* d_out, int out_size)
{
    const float* X   = (const float*)d_in[0];
    const int*   y   = (const int*)d_in[1];   // int32 (JAX x64 disabled)
    float*       out = (float*)d_out;

    const int total = in_sizes[0];          // N * C * T
    const int N     = in_sizes[1];          // 8192
    const int D     = total / N;            // 6144

    wcss_zero<<<1, 32>>>();

    {
        int chunks = (D + CPB - 1) / CPB;   // 24
        dim3 grid(chunks, KMAX);
        wcss_main<<<grid, TPB>>>(X, y, N, D);
    }

    wcss_final<<<1, 32>>>(D, out);
}

// round 11
// speedup vs baseline: 1.6697x; 1.2098x over previous
#include <cuda_runtime.h>
#include <cuda_bf16.h>

// WCSS: loss = mean_k [ (S2_k - ||S1_k||^2 / n_k) / (n_k * D) ]
//
// R10 post-mortem: low-occupancy register-complete design capped at
// ~4.3TB/s. R4's profile shows its high-occupancy main (atomic flush to
// per-class column sums) ran in ~11us; only its serial finalize was slow.
// R11 = R4 main (1680 blocks, 48 warps/SM) + parallel M2 reduce +
// 8-block scatter + end-of-call zeroing (globals are zero-init at load).

#define TPB   128            // threads per main block
#define CPB   (TPB * 2)      // 256 columns per block (float2/thread)
#define SEGR  128            // rows per segment
#define SLOT  2048           // g_order capacity per class
#define KMAX  16             // max classes (problem uses 10)
#define DMAX  8192           // max D (problem uses 6144)

__device__ float  g_colsum[KMAX * DMAX];  // per-class column sums
__device__ double g_S2[KMAX];             // per-class sum of squares
__device__ double g_M2[KMAX];             // per-class ||S1_k||^2
__device__ int    g_cnt[KMAX];
__device__ int    g_order[KMAX * SLOT];   // row ids, per-class slots

// ---------------------------------------------------------------------------
// grid = ceil(N/1024), block 1024. One label per thread. Per-warp smem
// histograms -> one global reservation atomic per (block,class) -> scatter.
__global__ void wcss_scatter(const int* __restrict__ y, int N)
{
    __shared__ int wcnt[32][KMAX];
    __shared__ int sbase[KMAX];

    const int tid  = threadIdx.x;
    const int w    = tid >> 5;
    const int lane = tid & 31;
    const int i    = blockIdx.x * 1024 + tid;

    if (lane < KMAX) wcnt[w][lane] = 0;
    __syncthreads();

    int lab = -1;
    if (i < N) {
        lab = __ldg(&y[i]) & (KMAX - 1);
        atomicAdd(&wcnt[w][lab], 1);
    }
    __syncthreads();

    // Thread k (<KMAX): exclusive prefix over warps + global reservation.
    if (tid < KMAX) {
        int acc = 0;
        #pragma unroll
        for (int w2 = 0; w2 < 32; w2++) {
            int v = wcnt[w2][tid];
            wcnt[w2][tid] = acc;
            acc += v;
        }
        sbase[tid] = atomicAdd(&g_cnt[tid], acc);
    }
    __syncthreads();
    if (lane < KMAX) wcnt[w][lane] += sbase[lane];
    __syncthreads();

    if (lab >= 0) {
        int pos = atomicAdd(&wcnt[w][lab], 1);
        if (pos < SLOT) g_order[lab * SLOT + pos] = i;
    }
}

// ---------------------------------------------------------------------------
// grid = (colChunks, KMAX, SEGS). Block (x, c, s): class c, rows
// [s*SEGR, ...) of its slot, 2 columns per thread. Register accumulators,
// flush: 2 spread float atomics per thread (colsum) + 1 double atomic (S2).
__global__ __launch_bounds__(TPB)
void wcss_main(const float* __restrict__ X, int D)
{
    const int c  = blockIdx.y;
    const int cn = min(g_cnt[c], SLOT);
    const int r0 = blockIdx.z * SEGR;
    if (r0 >= cn) return;
    const int len = min(SEGR, cn - r0);

    const int tid = threadIdx.x;

    __shared__ size_t offs[SEGR];       // byte offsets: row * D * 4
    if (tid < len)
        offs[tid] = (size_t)g_order[c * SLOT + r0 + tid] * (size_t)D * 4u;
    __syncthreads();

    const int d2 = blockIdx.x * CPB + tid * 2;
    float2 s = make_float2(0.f, 0.f);
    float2 q = make_float2(0.f, 0.f);

    if (d2 + 1 < D) {
        const char* __restrict__ bp = (const char*)X + (size_t)d2 * 4u;
        int i = 0;
        for (; i + 8 <= len; i += 8) {
            float2 x[8];
            #pragma unroll
            for (int u = 0; u < 8; u++)
                x[u] = __ldg((const float2*)(bp + offs[i + u]));
            #pragma unroll
            for (int u = 0; u < 8; u++) {
                s.x += x[u].x; q.x = fmaf(x[u].x, x[u].x, q.x);
                s.y += x[u].y; q.y = fmaf(x[u].y, x[u].y, q.y);
            }
        }
        for (; i < len; i++) {
            float2 x = __ldg((const float2*)(bp + offs[i]));
            s.x += x.x; q.x = fmaf(x.x, x.x, q.x);
            s.y += x.y; q.y = fmaf(x.y, x.y, q.y);
        }
        atomicAdd(&g_colsum[c * D + d2],     s.x);
        atomicAdd(&g_colsum[c * D + d2 + 1], s.y);
    } else if (d2 < D) {
        for (int i = 0; i < len; i++) {
            float xv = __ldg((const float*)((const char*)X + offs[i]) + d2);
            s.x += xv; q.x = fmaf(xv, xv, q.x);
        }
        atomicAdd(&g_colsum[c * D + d2], s.x);
    }

    // Block-reduce sumsq -> one double atomic.
    float qt = q.x + q.y;
    #pragma unroll
    for (int o = 16; o > 0; o >>= 1)
        qt += __shfl_down_sync(0xffffffffu, qt, o);

    __shared__ float qs[TPB / 32];
    if ((tid & 31) == 0) qs[tid >> 5] = qt;
    __syncthreads();
    if (tid == 0) {
        float qv = 0.f;
        #pragma unroll
        for (int w = 0; w < TPB / 32; w++) qv += qs[w];
        atomicAdd(&g_S2[c], (double)qv);
    }
}

// ---------------------------------------------------------------------------
// grid = (colChunks, KMAX): square + reduce colsum -> g_M2[c]. Parallel
// replacement for R4's 126us serial finalize.
__global__ __launch_bounds__(TPB)
void wcss_m2red(int D)
{
    const int c   = blockIdx.y;
    const int tid = threadIdx.x;
    const int d2  = blockIdx.x * CPB + tid * 2;

    float m2 = 0.f;
    if (d2 + 1 < D) {
        float vx = g_colsum[c * D + d2];
        float vy = g_colsum[c * D + d2 + 1];
        m2 = vx * vx + vy * vy;
    } else if (d2 < D) {
        float vx = g_colsum[c * D + d2];
        m2 = vx * vx;
    }

    #pragma unroll
    for (int o = 16; o > 0; o >>= 1)
        m2 += __shfl_down_sync(0xffffffffu, m2, o);

    __shared__ float ms[TPB / 32];
    if ((tid & 31) == 0) ms[tid >> 5] = m2;
    __syncthreads();
    if (tid == 0) {
        float mv = 0.f;
        #pragma unroll
        for (int w = 0; w < TPB / 32; w++) mv += ms[w];
        atomicAdd(&g_M2[c], (double)mv);
    }
}

// ---------------------------------------------------------------------------
// grid = ceil(KMAX*D/256): block 0 computes the scalar output, then ALL
// blocks zero the accumulators for the next invocation (device globals are
// zero-initialized at module load, so call 1 is clean too).
__global__ void wcss_final(int D, float* __restrict__ out)
{
    const int tid = threadIdx.x;

    if (blockIdx.x == 0 && tid == 0) {
        double total = 0.0;
        int    nc    = 0;
        for (int k = 0; k < KMAX; k++) {
            int c = min(g_cnt[k], SLOT);
            if (c == 0) continue;
            double n = (double)c;
            total += (g_S2[k] - g_M2[k] / n) / (n * (double)D);
            nc++;
        }
        out[0] = (float)(total / (double)(nc > 0 ? nc : 1));
    }
    __syncthreads();   // block 0: out written before its zeroing proceeds

    int idx = blockIdx.x * 256 + tid;
    if (idx < KMAX * D) g_colsum[idx] = 0.f;
    if (blockIdx.x == 0 && tid < KMAX) {
        g_S2[tid] = 0.0;
        g_M2[tid] = 0.0;
        g_cnt[tid] = 0;
    }
}

// ---------------------------------------------------------------------------
extern "C" void kernel_launch(void* const* d_in, const int* in_sizes, int n_in,
                              void* d_out, int out_size)
{
    const float* X   = (const float*)d_in[0];
    const int*   y   = (const int*)d_in[1];   // int32 (JAX x64 disabled)
    float*       out = (float*)d_out;

    const int total = in_sizes[0];          // N * C * T
    const int N     = in_sizes[1];          // 8192
    const int D     = total / N;            // 6144

    wcss_scatter<<<(N + 1023) / 1024, 1024>>>(y, N);

    {
        int chunks = (D + CPB - 1) / CPB;       // 24
        int segs   = (SLOT + SEGR - 1) / SEGR;  // 16
        dim3 grid(chunks, KMAX, segs);
        wcss_main<<<grid, TPB>>>(X, D);
    }

    {
        int chunks = (D + CPB - 1) / CPB;
        dim3 grid(chunks, KMAX);
        wcss_m2red<<<grid, TPB>>>(D);
    }

    wcss_final<<<(KMAX * D + 255) / 256, 256>>>(D, out);
}

// round 12
// speedup vs baseline: 1.9792x; 1.1853x over previous
#include <cuda_runtime.h>
#include <cuda_bf16.h>

// WCSS: loss = mean_k [ (S2_k - ||S1_k||^2 / n_k) / (n_k * D) ]
//
// R11 post-mortem: main is at the DRAM floor (~26us); wcss_final burned
// 12.6us on ONE thread doing 48 serial dependent global loads. R12: the
// per-class scalars are loaded by 16 threads in parallel and reduced with
// shuffles -> final ~1.5us. Everything else unchanged.

#define TPB   128            // threads per main block
#define CPB   (TPB * 2)      // 256 columns per block (float2/thread)
#define SEGR  128            // rows per segment
#define SLOT  2048           // g_order capacity per class
#define KMAX  16             // max classes (problem uses 10)
#define DMAX  8192           // max D (problem uses 6144)

__device__ float  g_colsum[KMAX * DMAX];  // per-class column sums
__device__ double g_S2[KMAX];             // per-class sum of squares
__device__ double g_M2[KMAX];             // per-class ||S1_k||^2
__device__ int    g_cnt[KMAX];
__device__ int    g_order[KMAX * SLOT];   // row ids, per-class slots

// ---------------------------------------------------------------------------
// grid = ceil(N/1024), block 1024. One label per thread. Per-warp smem
// histograms -> one global reservation atomic per (block,class) -> scatter.
__global__ void wcss_scatter(const int* __restrict__ y, int N)
{
    __shared__ int wcnt[32][KMAX];
    __shared__ int sbase[KMAX];

    const int tid  = threadIdx.x;
    const int w    = tid >> 5;
    const int lane = tid & 31;
    const int i    = blockIdx.x * 1024 + tid;

    if (lane < KMAX) wcnt[w][lane] = 0;
    __syncthreads();

    int lab = -1;
    if (i < N) {
        lab = __ldg(&y[i]) & (KMAX - 1);
        atomicAdd(&wcnt[w][lab], 1);
    }
    __syncthreads();

    // Thread k (<KMAX): exclusive prefix over warps + global reservation.
    if (tid < KMAX) {
        int acc = 0;
        #pragma unroll
        for (int w2 = 0; w2 < 32; w2++) {
            int v = wcnt[w2][tid];
            wcnt[w2][tid] = acc;
            acc += v;
        }
        sbase[tid] = atomicAdd(&g_cnt[tid], acc);
    }
    __syncthreads();
    if (lane < KMAX) wcnt[w][lane] += sbase[lane];
    __syncthreads();

    if (lab >= 0) {
        int pos = atomicAdd(&wcnt[w][lab], 1);
        if (pos < SLOT) g_order[lab * SLOT + pos] = i;
    }
}

// ---------------------------------------------------------------------------
// grid = (colChunks, KMAX, SEGS). Block (x, c, s): class c, rows
// [s*SEGR, ...) of its slot, 2 columns per thread. Register accumulators,
// flush: 2 spread float atomics per thread (colsum) + 1 double atomic (S2).
__global__ __launch_bounds__(TPB)
void wcss_main(const float* __restrict__ X, int D)
{
    const int c  = blockIdx.y;
    const int cn = min(g_cnt[c], SLOT);
    const int r0 = blockIdx.z * SEGR;
    if (r0 >= cn) return;
    const int len = min(SEGR, cn - r0);

    const int tid = threadIdx.x;

    __shared__ size_t offs[SEGR];       // byte offsets: row * D * 4
    if (tid < len)
        offs[tid] = (size_t)g_order[c * SLOT + r0 + tid] * (size_t)D * 4u;
    __syncthreads();

    const int d2 = blockIdx.x * CPB + tid * 2;
    float2 s = make_float2(0.f, 0.f);
    float2 q = make_float2(0.f, 0.f);

    if (d2 + 1 < D) {
        const char* __restrict__ bp = (const char*)X + (size_t)d2 * 4u;
        int i = 0;
        for (; i + 8 <= len; i += 8) {
            float2 x[8];
            #pragma unroll
            for (int u = 0; u < 8; u++)
                x[u] = __ldg((const float2*)(bp + offs[i + u]));
            #pragma unroll
            for (int u = 0; u < 8; u++) {
                s.x += x[u].x; q.x = fmaf(x[u].x, x[u].x, q.x);
                s.y += x[u].y; q.y = fmaf(x[u].y, x[u].y, q.y);
            }
        }
        for (; i < len; i++) {
            float2 x = __ldg((const float2*)(bp + offs[i]));
            s.x += x.x; q.x = fmaf(x.x, x.x, q.x);
            s.y += x.y; q.y = fmaf(x.y, x.y, q.y);
        }
        atomicAdd(&g_colsum[c * D + d2],     s.x);
        atomicAdd(&g_colsum[c * D + d2 + 1], s.y);
    } else if (d2 < D) {
        for (int i = 0; i < len; i++) {
            float xv = __ldg((const float*)((const char*)X + offs[i]) + d2);
            s.x += xv; q.x = fmaf(xv, xv, q.x);
        }
        atomicAdd(&g_colsum[c * D + d2], s.x);
    }

    // Block-reduce sumsq -> one double atomic.
    float qt = q.x + q.y;
    #pragma unroll
    for (int o = 16; o > 0; o >>= 1)
        qt += __shfl_down_sync(0xffffffffu, qt, o);

    __shared__ float qs[TPB / 32];
    if ((tid & 31) == 0) qs[tid >> 5] = qt;
    __syncthreads();
    if (tid == 0) {
        float qv = 0.f;
        #pragma unroll
        for (int w = 0; w < TPB / 32; w++) qv += qs[w];
        atomicAdd(&g_S2[c], (double)qv);
    }
}

// ---------------------------------------------------------------------------
// grid = (colChunks, KMAX): square + reduce colsum -> g_M2[c].
__global__ __launch_bounds__(TPB)
void wcss_m2red(int D)
{
    const int c   = blockIdx.y;
    const int tid = threadIdx.x;
    const int d2  = blockIdx.x * CPB + tid * 2;

    float m2 = 0.f;
    if (d2 + 1 < D) {
        float vx = g_colsum[c * D + d2];
        float vy = g_colsum[c * D + d2 + 1];
        m2 = vx * vx + vy * vy;
    } else if (d2 < D) {
        float vx = g_colsum[c * D + d2];
        m2 = vx * vx;
    }

    #pragma unroll
    for (int o = 16; o > 0; o >>= 1)
        m2 += __shfl_down_sync(0xffffffffu, m2, o);

    __shared__ float ms[TPB / 32];
    if ((tid & 31) == 0) ms[tid >> 5] = m2;
    __syncthreads();
    if (tid == 0) {
        float mv = 0.f;
        #pragma unroll
        for (int w = 0; w < TPB / 32; w++) mv += ms[w];
        atomicAdd(&g_M2[c], (double)mv);
    }
}

// ---------------------------------------------------------------------------
// grid = ceil(KMAX*D/256). Block 0, warp 0: threads 0..KMAX-1 load their
// class's scalars IN PARALLEL (one memory round-trip, not 48 serial),
// shuffle-reduce (sum lk, count classes), lane 0 writes out. All blocks
// then zero the accumulators for the next invocation (device globals are
// zero-initialized at module load, so call 1 is clean too).
__global__ void wcss_final(int D, float* __restrict__ out)
{
    const int tid = threadIdx.x;

    if (blockIdx.x == 0 && tid < 32) {
        double lk = 0.0;
        int    present = 0;
        if (tid < KMAX) {
            int c = min(g_cnt[tid], SLOT);           // parallel loads
            if (c > 0) {
                double n = (double)c;
                lk = (g_S2[tid] - g_M2[tid] / n) / (n * (double)D);
                present = 1;
            }
        }
        #pragma unroll
        for (int o = 8; o > 0; o >>= 1) {
            lk      += __shfl_down_sync(0xffffffffu, lk, o);
            present += __shfl_down_sync(0xffffffffu, present, o);
        }
        if (tid == 0)
            out[0] = (float)(lk / (double)(present > 0 ? present : 1));
    }
    __syncthreads();   // block 0: out computed before its zeroing proceeds

    int idx = blockIdx.x * 256 + tid;
    if (idx < KMAX * D) g_colsum[idx] = 0.f;
    if (blockIdx.x == 0 && tid < KMAX) {
        g_S2[tid] = 0.0;
        g_M2[tid] = 0.0;
        g_cnt[tid] = 0;
    }
}

// ---------------------------------------------------------------------------
extern "C" void kernel_launch(void* const* d_in, const int* in_sizes, int n_in,
                              void* d_out, int out_size)
{
    const float* X   = (const float*)d_in[0];
    const int*   y   = (const int*)d_in[1];   // int32 (JAX x64 disabled)
    float*       out = (float*)d_out;

    const int total = in_sizes[0];          // N * C * T
    const int N     = in_sizes[1];          // 8192
    const int D     = total / N;            // 6144

    wcss_scatter<<<(N + 1023) / 1024, 1024>>>(y, N);

    {
        int chunks = (D + CPB - 1) / CPB;       // 24
        int segs   = (SLOT + SEGR - 1) / SEGR;  // 16
        dim3 grid(chunks, KMAX, segs);
        wcss_main<<<grid, TPB>>>(X, D);
    }

    {
        int chunks = (D + CPB - 1) / CPB;
        dim3 grid(chunks, KMAX);
        wcss_m2red<<<grid, TPB>>>(D);
    }

    wcss_final<<<(KMAX * D + 255) / 256, 256>>>(D, out);
}